// round 14
// baseline (speedup 1.0000x reference)
#include <cuda_runtime.h>
#include <cuda_bf16.h>
#include <cuda_fp16.h>
#include <math.h>

// Problem constants
#define NN 50000
#define EE 1600000
#define GG 512
#define INF_ 128
#define HID 128
#define PROJ 256
#define NPART 128   // >= ceil(NN/512)

// ---------------- device scratch, duplicated per encoder ----------------
// All vector-cast arrays first (16B-multiple sizes); odd-sized off[] last.
struct alignas(16) EncScratch {
    __half Ph[NN * HID];      // fp16 prescaled features dinv[u]*(A@W)[u]
    float Ha[NN * HID];
    float Hb[NN * HID];
    float pool[GG * HID];
    float t [GG * PROJ];
    float t2[GG * PROJ];
    float q [GG * (PROJ/2)];
    float dinv[NN];
    int   cnt[NN];
    int   csr[EE];
    int   part[NPART];
    int   off[NN + 1];        // odd size -> keep last
};
__device__ EncScratch g_e0;
__device__ EncScratch g_e1;

// ---------------- CSR build ----------------
__global__ void k_zero(int* cnt, int n) {
    int i = blockIdx.x * blockDim.x + threadIdx.x;
    if (i < n) cnt[i] = 0;
}

__global__ void k_degree(const int* __restrict__ dst, int* cnt, int e) {
    int i = blockIdx.x * blockDim.x + threadIdx.x;
    if (i < e) atomicAdd(&cnt[dst[i]], 1);
}

__global__ void k_part(const int* __restrict__ cnt, int* part, int n) {
    __shared__ int red[16];
    int i = blockIdx.x * blockDim.x + threadIdx.x;
    int v = (i < n) ? cnt[i] : 0;
    int lane = threadIdx.x & 31, wid = threadIdx.x >> 5;
    #pragma unroll
    for (int o = 16; o; o >>= 1) v += __shfl_down_sync(0xffffffffu, v, o);
    if (lane == 0) red[wid] = v;
    __syncthreads();
    if (wid == 0) {
        int s = (lane < (blockDim.x >> 5)) ? red[lane] : 0;
        #pragma unroll
        for (int o = 16; o; o >>= 1) s += __shfl_down_sync(0xffffffffu, s, o);
        if (lane == 0) part[blockIdx.x] = s;
    }
}

__global__ void k_scanpart(int* part, int nb) {
    __shared__ int sh[NPART];
    int tid = threadIdx.x;
    sh[tid] = (tid < nb) ? part[tid] : 0;
    __syncthreads();
    for (int d = 1; d < NPART; d <<= 1) {
        int v = (tid >= d) ? sh[tid - d] : 0;
        __syncthreads();
        sh[tid] += v;
        __syncthreads();
    }
    if (tid < nb) part[tid] = (tid == 0) ? 0 : sh[tid - 1];
}

__global__ void k_off(int* cnt, const int* __restrict__ part, int* off,
                      float* dinv, int n) {
    __shared__ int wsum[16];
    int i = blockIdx.x * blockDim.x + threadIdx.x;
    int lane = threadIdx.x & 31, wid = threadIdx.x >> 5;
    int nw = blockDim.x >> 5;
    int v = (i < n) ? cnt[i] : 0;
    int x = v;
    #pragma unroll
    for (int d = 1; d < 32; d <<= 1) {
        int y = __shfl_up_sync(0xffffffffu, x, d);
        if (lane >= d) x += y;
    }
    if (lane == 31) wsum[wid] = x;
    __syncthreads();
    if (wid == 0) {
        int s = (lane < nw) ? wsum[lane] : 0;
        #pragma unroll
        for (int d = 1; d < 32; d <<= 1) {
            int y = __shfl_up_sync(0xffffffffu, s, d);
            if (lane >= d) s += y;
        }
        wsum[lane] = s;
    }
    __syncthreads();
    int excl = x - v + ((wid == 0) ? 0 : wsum[wid - 1]) + part[blockIdx.x];
    if (i < n) {
        off[i]  = excl;
        dinv[i] = rsqrtf((float)(v + 1));
        cnt[i]  = excl;          // cursor for fill
        if (i == n - 1) off[n] = excl + v;
    }
}

__global__ void k_fill(const int* __restrict__ src, const int* __restrict__ dst,
                       int* cnt, int* csr, int e) {
    int i = blockIdx.x * blockDim.x + threadIdx.x;
    if (i < e) {
        int d = dst[i];
        int pos = atomicAdd(&cnt[d], 1);
        csr[pos] = src[i];
    }
}

// ---------------- packed-f32x2 GEMM + dinv prescale + fp16 epilogue ---------
// out_h[r][c] = half( dinv[r] * (A[r,:]@W[:,c]) )
__device__ __forceinline__ void fma_f32x2(unsigned long long& d,
                                          unsigned long long a,
                                          unsigned long long b) {
    asm("fma.rn.f32x2 %0, %1, %2, %0;" : "+l"(d) : "l"(a), "l"(b));
}

__global__ __launch_bounds__(256) void k_gemm_p2(
        const float* __restrict__ A, const float* __restrict__ W,
        const float* __restrict__ dinv, __half* __restrict__ out, int M) {
    extern __shared__ float sm[];
    float2* Ws2 = (float2*)sm;            // [64][128] float2 = 64KB
    float*  As  = sm + 64 * 128 * 2;      // [64][128] float  = 32KB
    int tid = threadIdx.x;

    for (int i = tid; i < 64 * 32; i += 256) {
        int kp = i >> 5, c4 = i & 31;
        float4 w0 = ((const float4*)W)[(2 * kp)     * 32 + c4];
        float4 w1 = ((const float4*)W)[(2 * kp + 1) * 32 + c4];
        float2* dstp = Ws2 + kp * 128 + (c4 << 2);
        dstp[0] = make_float2(w0.x, w1.x);
        dstp[1] = make_float2(w0.y, w1.y);
        dstp[2] = make_float2(w0.z, w1.z);
        dstp[3] = make_float2(w0.w, w1.w);
    }
    int rowbase = blockIdx.x * 64;
    for (int i = tid; i < 64 * 32; i += 256) {
        int r = i >> 5, c4 = i & 31;
        float4 v = make_float4(0.f, 0.f, 0.f, 0.f);
        if (rowbase + r < M) v = ((const float4*)A)[(rowbase + r) * 32 + c4];
        *(float4*)(As + r * 128 + (c4 << 2)) = v;
    }
    __syncthreads();

    int lane = tid & 31, w = tid >> 5;
    unsigned long long acc[8][4];
    #pragma unroll
    for (int r = 0; r < 8; r++)
        #pragma unroll
        for (int j = 0; j < 4; j++) acc[r][j] = 0ull;

    const unsigned long long* Wsu = (const unsigned long long*)Ws2;
    #pragma unroll 4
    for (int kp = 0; kp < 64; kp++) {
        unsigned long long w2[4];
        #pragma unroll
        for (int j = 0; j < 4; j++) w2[j] = Wsu[kp * 128 + lane + 32 * j];
        #pragma unroll
        for (int r = 0; r < 8; r++) {
            unsigned long long a2 =
                *(const unsigned long long*)(As + (w + r * 8) * 128 + 2 * kp);
            #pragma unroll
            for (int j = 0; j < 4; j++) fma_f32x2(acc[r][j], a2, w2[j]);
        }
    }

    #pragma unroll
    for (int r = 0; r < 8; r++) {
        int row = rowbase + w + r * 8;
        if (row < M) {
            float dv = dinv[row];
            #pragma unroll
            for (int j = 0; j < 4; j++) {
                unsigned long long u = acc[r][j];
                float lo = __uint_as_float((unsigned int)(u & 0xffffffffu));
                float hi = __uint_as_float((unsigned int)(u >> 32));
                out[row * 128 + lane + 32 * j] = __float2half_rn(dv * (lo + hi));
            }
        }
    }
}
#define GEMM_SMEM ((64 * 128 * 2 + 64 * 128) * sizeof(float))

// ---------------- gather: HALF-WARP per edge (2 edges per iteration) --------
// P rows are 256B = 16 uint4. Lanes 0-15 handle even edges, 16-31 odd edges;
// each half-lane loads uint4 (8 halfs = features 8*hl..8*hl+7).
// After the loop, shfl_xor(16) folds halves; all 32 lanes store one float4.
__global__ void k_gather(const uint4* __restrict__ P, const float* __restrict__ bias,
                         const float4* __restrict__ Hres, float4* __restrict__ out,
                         const int* __restrict__ off, const int* __restrict__ csr,
                         const float* __restrict__ dinv, int n, int mode) {
    int gw = (blockIdx.x * blockDim.x + threadIdx.x) >> 5;
    if (gw >= n) return;
    int lane = threadIdx.x & 31;
    int hl = lane & 15, side = lane >> 4;
    int v = gw;
    int off0 = off[v], off1 = off[v + 1];
    float dv = dinv[v];

    float a0, a1, a2, a3, a4, a5, a6, a7;
    // self term P[v]: side 0 only (side 1 starts at zero)
    {
        uint4 s = P[v * 16 + hl];
        const __half2* h = (const __half2*)&s;
        float2 f0 = __half22float2(h[0]);
        float2 f1 = __half22float2(h[1]);
        float2 f2 = __half22float2(h[2]);
        float2 f3 = __half22float2(h[3]);
        float m0 = side ? 0.f : 1.f;
        a0 = m0 * f0.x; a1 = m0 * f0.y; a2 = m0 * f1.x; a3 = m0 * f1.y;
        a4 = m0 * f2.x; a5 = m0 * f2.y; a6 = m0 * f3.x; a7 = m0 * f3.y;
    }

    for (int j = off0; j < off1; j += 32) {
        int idx = j + lane;
        int u = (idx < off1) ? csr[idx] : -1;
        int m = off1 - j; if (m > 32) m = 32;
        #pragma unroll 4
        for (int i = 0; i < m; i += 2) {
            int u0 = __shfl_sync(0xffffffffu, u, i);
            int u1 = __shfl_sync(0xffffffffu, u, i + 1);
            int uu = side ? u1 : u0;
            if (uu >= 0) {
                uint4 h4 = P[uu * 16 + hl];
                const __half2* hh = (const __half2*)&h4;
                float2 f0 = __half22float2(hh[0]);
                float2 f1 = __half22float2(hh[1]);
                float2 f2 = __half22float2(hh[2]);
                float2 f3 = __half22float2(hh[3]);
                a0 += f0.x; a1 += f0.y; a2 += f1.x; a3 += f1.y;
                a4 += f2.x; a5 += f2.y; a6 += f3.x; a7 += f3.y;
            }
        }
    }

    // fold the two halves: both sides end with the full sum
    a0 += __shfl_xor_sync(0xffffffffu, a0, 16);
    a1 += __shfl_xor_sync(0xffffffffu, a1, 16);
    a2 += __shfl_xor_sync(0xffffffffu, a2, 16);
    a3 += __shfl_xor_sync(0xffffffffu, a3, 16);
    a4 += __shfl_xor_sync(0xffffffffu, a4, 16);
    a5 += __shfl_xor_sync(0xffffffffu, a5, 16);
    a6 += __shfl_xor_sync(0xffffffffu, a6, 16);
    a7 += __shfl_xor_sync(0xffffffffu, a7, 16);

    // lane (hl, side) stores float4 index 2*hl+side = features 8hl+4side..+3
    float s0 = side ? a4 : a0;
    float s1 = side ? a5 : a1;
    float s2 = side ? a6 : a2;
    float s3 = side ? a7 : a3;

    int ci = 2 * hl + side;
    const float4* b4 = (const float4*)bias;
    float4 bb = b4[ci];
    float4 r;
    r.x = fmaxf(fmaf(dv, s0, bb.x), 0.f);
    r.y = fmaxf(fmaf(dv, s1, bb.y), 0.f);
    r.z = fmaxf(fmaf(dv, s2, bb.z), 0.f);
    r.w = fmaxf(fmaf(dv, s3, bb.w), 0.f);
    if (mode == 1) {
        float4 h = Hres[v * 32 + ci];
        r.x += h.x; r.y += h.y; r.z += h.z; r.w += h.w;
    }
    out[v * 32 + ci] = r;
}

// ---------------- pooling (binary-search bounds) ----------------------------
__global__ void k_pool(const float4* __restrict__ H, float4* __restrict__ pool,
                       const int* __restrict__ batch, int n, int g) {
    int gw = (blockIdx.x * blockDim.x + threadIdx.x) >> 5;
    if (gw >= g) return;
    int lane = threadIdx.x & 31;
    int lo = 0, hi = n;
    while (lo < hi) { int mid = (lo + hi) >> 1; if (batch[mid] < gw) lo = mid + 1; else hi = mid; }
    int s = lo;
    hi = n;
    while (lo < hi) { int mid = (lo + hi) >> 1; if (batch[mid] < gw + 1) lo = mid + 1; else hi = mid; }
    int e = lo;
    float4 acc = make_float4(0.f, 0.f, 0.f, 0.f);
    for (int r = s; r < e; r++) {
        float4 v = H[r * 32 + lane];
        acc.x += v.x; acc.y += v.y; acc.z += v.z; acc.w += v.w;
    }
    float sc = (e > s) ? 1.0f / (float)(e - s) : 0.f;
    pool[gw * 32 + lane] = make_float4(acc.x * sc, acc.y * sc, acc.z * sc, acc.w * sc);
}

// ---------------- small GEMM: warp per row ----------------
template <int NPER>
__global__ void k_gemm_small(const float* __restrict__ A, const float* __restrict__ W,
                             const float* __restrict__ bias, float* __restrict__ out,
                             int M, int K, int N, int relu) {
    int gw = (blockIdx.x * blockDim.x + threadIdx.x) >> 5;
    if (gw >= M) return;
    int lane = threadIdx.x & 31;
    float acc[NPER];
    #pragma unroll
    for (int j = 0; j < NPER; j++) acc[j] = 0.f;
    const float* a = A + gw * K;
    for (int k = 0; k < K; k++) {
        float av = __ldg(a + k);
        const float* wr = W + k * N;
        #pragma unroll
        for (int j = 0; j < NPER; j++) acc[j] += av * __ldg(wr + lane + 32 * j);
    }
    #pragma unroll
    for (int j = 0; j < NPER; j++) {
        float v = acc[j] + bias[lane + 32 * j];
        if (relu) v = fmaxf(v, 0.f);
        out[gw * N + lane + 32 * j] = v;
    }
}

// ---------------- batchnorm ----------------
__global__ void k_bn(const float* __restrict__ x, const float* __restrict__ gamma,
                     const float* __restrict__ beta, float* __restrict__ out,
                     int rows, int cols, int relu) {
    int col = blockIdx.x;
    int tid = threadIdx.x, lane = tid & 31, wid = tid >> 5;
    __shared__ float red[8];
    __shared__ float s_m, s_inv;
    float s = 0.f, s2 = 0.f;
    for (int r = tid; r < rows; r += blockDim.x) {
        float v = x[r * cols + col];
        s += v; s2 += v * v;
    }
    #pragma unroll
    for (int o = 16; o; o >>= 1) {
        s  += __shfl_down_sync(0xffffffffu, s, o);
        s2 += __shfl_down_sync(0xffffffffu, s2, o);
    }
    if (lane == 0) { red[wid] = s; red[4 + wid] = s2; }
    __syncthreads();
    if (tid == 0) {
        float ts = red[0] + red[1] + red[2] + red[3];
        float t2 = red[4] + red[5] + red[6] + red[7];
        float m = ts / rows;
        float var = t2 / rows - m * m;
        s_m = m;
        s_inv = rsqrtf(var + 1e-5f);
    }
    __syncthreads();
    float m = s_m, inv = s_inv, ga = gamma[col], be = beta[col];
    for (int r = tid; r < rows; r += blockDim.x) {
        float v = ga * (x[r * cols + col] - m) * inv + be;
        if (relu) v = fmaxf(v, 0.f);
        out[r * cols + col] = v;
    }
}

// ---------------- host orchestration ----------------
struct HeadW {
    const float *Wp1, *bp1, *ga1, *be1, *Wp2, *bp2, *ga2, *be2;
    const float *Wq1, *bq1, *Wq2, *bq2;
};

static void run_encoder_and_head(cudaStream_t st, EncScratch* S,
        const float* x, const int* ei, const int* batch,
        const float* W1, const float* b1, const float* W2, const float* b2,
        const float* W3, const float* b3, const HeadW& hw,
        float* pout, float* zout, int n, int e, int g) {
    const int* src = ei;
    const int* dst = ei + e;

    int tb = 256;
    int nb512 = (n + 511) / 512;
    k_zero  <<<(n + tb - 1) / tb, tb, 0, st>>>(S->cnt, n);
    k_degree<<<(e + tb - 1) / tb, tb, 0, st>>>(dst, S->cnt, e);
    k_part  <<<nb512, 512, 0, st>>>(S->cnt, S->part, n);
    k_scanpart<<<1, NPART, 0, st>>>(S->part, nb512);
    k_off   <<<nb512, 512, 0, st>>>(S->cnt, S->part, S->off, S->dinv, n);
    k_fill  <<<(e + tb - 1) / tb, tb, 0, st>>>(src, dst, S->cnt, S->csr, e);

    int gemm_grid = (n + 63) / 64;
    int gath_grid = (n * 32 + tb - 1) / tb;

    const uint4* Ph = (const uint4*)S->Ph;
    float4* Ha = (float4*)S->Ha;
    float4* Hb = (float4*)S->Hb;

    k_gemm_p2<<<gemm_grid, 256, GEMM_SMEM, st>>>(x, W1, S->dinv, S->Ph, n);
    k_gather<<<gath_grid, tb, 0, st>>>(Ph, b1, nullptr, Ha, S->off, S->csr, S->dinv, n, 0);
    k_gemm_p2<<<gemm_grid, 256, GEMM_SMEM, st>>>(S->Ha, W2, S->dinv, S->Ph, n);
    k_gather<<<gath_grid, tb, 0, st>>>(Ph, b2, (const float4*)Ha, Hb, S->off, S->csr, S->dinv, n, 1);
    k_gemm_p2<<<gemm_grid, 256, GEMM_SMEM, st>>>(S->Hb, W3, S->dinv, S->Ph, n);
    k_gather<<<gath_grid, tb, 0, st>>>(Ph, b3, (const float4*)Hb, Ha, S->off, S->csr, S->dinv, n, 1);

    k_pool<<<(g * 32 + tb - 1) / tb, tb, 0, st>>>((const float4*)Ha, (float4*)S->pool,
                                                  batch, n, g);

    // head
    int gw_blocks = (g * 32 + 255) / 256;
    k_gemm_small<8><<<gw_blocks, 256, 0, st>>>(S->pool, hw.Wp1, hw.bp1, S->t, g, HID, PROJ, 0);
    k_bn<<<PROJ, 128, 0, st>>>(S->t, hw.ga1, hw.be1, S->t, g, PROJ, 1);
    k_gemm_small<8><<<gw_blocks, 256, 0, st>>>(S->t, hw.Wp2, hw.bp2, S->t2, g, PROJ, PROJ, 0);
    k_bn<<<PROJ, 128, 0, st>>>(S->t2, hw.ga2, hw.be2, zout, g, PROJ, 0);
    k_gemm_small<4><<<gw_blocks, 256, 0, st>>>(zout, hw.Wq1, hw.bq1, S->q, g, PROJ, PROJ / 2, 1);
    k_gemm_small<8><<<gw_blocks, 256, 0, st>>>(S->q, hw.Wq2, hw.bq2, pout, g, PROJ / 2, PROJ, 0);
}

extern "C" void kernel_launch(void* const* d_in, const int* in_sizes, int n_in,
                              void* d_out, int out_size) {
    const float* x1  = (const float*)d_in[0];
    const int*   ei1 = (const int*)  d_in[1];
    const int*   bt1 = (const int*)  d_in[2];
    const float* x2  = (const float*)d_in[3];
    const int*   ei2 = (const int*)  d_in[4];
    const int*   bt2 = (const int*)  d_in[5];
    const float* W1  = (const float*)d_in[6];
    const float* b1  = (const float*)d_in[7];
    const float* W2  = (const float*)d_in[8];
    const float* b2  = (const float*)d_in[9];
    const float* W3  = (const float*)d_in[10];
    const float* b3  = (const float*)d_in[11];
    HeadW hw;
    hw.Wp1 = (const float*)d_in[12]; hw.bp1 = (const float*)d_in[13];
    hw.ga1 = (const float*)d_in[14]; hw.be1 = (const float*)d_in[15];
    hw.Wp2 = (const float*)d_in[16]; hw.bp2 = (const float*)d_in[17];
    hw.ga2 = (const float*)d_in[18]; hw.be2 = (const float*)d_in[19];
    hw.Wq1 = (const float*)d_in[20]; hw.bq1 = (const float*)d_in[21];
    hw.Wq2 = (const float*)d_in[22]; hw.bq2 = (const float*)d_in[23];

    int n = in_sizes[0] / INF_;
    int e = in_sizes[1] / 2;
    int g = GG;

    static bool init = false;
    static cudaStream_t s2;
    static cudaEvent_t evFork, evJoin;
    if (!init) {
        cudaStreamCreateWithFlags(&s2, cudaStreamNonBlocking);
        cudaEventCreateWithFlags(&evFork, cudaEventDisableTiming);
        cudaEventCreateWithFlags(&evJoin, cudaEventDisableTiming);
        cudaFuncSetAttribute(k_gemm_p2, cudaFuncAttributeMaxDynamicSharedMemorySize,
                             GEMM_SMEM);
        init = true;
    }

    EncScratch *S0, *S1;
    cudaGetSymbolAddress((void**)&S0, g_e0);
    cudaGetSymbolAddress((void**)&S1, g_e1);

    float* out = (float*)d_out;
    float* p1 = out;
    float* p2 = out + g * PROJ;
    float* z1 = out + 2 * g * PROJ;
    float* z2 = out + 3 * g * PROJ;

    // fork
    cudaEventRecord(evFork, 0);
    cudaStreamWaitEvent(s2, evFork, 0);

    run_encoder_and_head(0,  S0, x1, ei1, bt1, W1, b1, W2, b2, W3, b3, hw, p1, z1, n, e, g);
    run_encoder_and_head(s2, S1, x2, ei2, bt2, W1, b1, W2, b2, W3, b3, hw, p2, z2, n, e, g);

    // join
    cudaEventRecord(evJoin, s2);
    cudaStreamWaitEvent(0, evJoin, 0);
}

// round 16
// speedup vs baseline: 1.0638x; 1.0638x over previous
#include <cuda_runtime.h>
#include <cuda_bf16.h>
#include <cuda_fp16.h>
#include <math.h>

// Problem constants
#define NN 50000
#define EE 1600000
#define GG 512
#define INF_ 128
#define HID 128
#define PROJ 256
#define NPART 128   // >= ceil(NN/512)

// ---------------- device scratch, duplicated per encoder ----------------
// All vector-cast arrays first (16B-multiple sizes); odd-sized off[] last.
struct alignas(16) EncScratch {
    __half Ph[NN * HID];      // fp16 prescaled features dinv[u]*(A@W)[u]
    __half Ha[NN * HID];      // fp16 hidden states (halved footprint: fits L2)
    __half Hb[NN * HID];
    float pool[GG * HID];
    float t [GG * PROJ];
    float t2[GG * PROJ];
    float q [GG * (PROJ/2)];
    float dinv[NN];
    int   cnt[NN];
    int   csr[EE];
    int   part[NPART];
    int   off[NN + 1];        // odd size -> keep last
};
__device__ EncScratch g_e0;
__device__ EncScratch g_e1;

// ---------------- CSR build ----------------
__global__ void k_zero(int* cnt, int n) {
    int i = blockIdx.x * blockDim.x + threadIdx.x;
    if (i < n) cnt[i] = 0;
}

__global__ void k_degree(const int* __restrict__ dst, int* cnt, int e) {
    int i = blockIdx.x * blockDim.x + threadIdx.x;
    if (i < e) atomicAdd(&cnt[dst[i]], 1);
}

__global__ void k_part(const int* __restrict__ cnt, int* part, int n) {
    __shared__ int red[16];
    int i = blockIdx.x * blockDim.x + threadIdx.x;
    int v = (i < n) ? cnt[i] : 0;
    int lane = threadIdx.x & 31, wid = threadIdx.x >> 5;
    #pragma unroll
    for (int o = 16; o; o >>= 1) v += __shfl_down_sync(0xffffffffu, v, o);
    if (lane == 0) red[wid] = v;
    __syncthreads();
    if (wid == 0) {
        int s = (lane < (blockDim.x >> 5)) ? red[lane] : 0;
        #pragma unroll
        for (int o = 16; o; o >>= 1) s += __shfl_down_sync(0xffffffffu, s, o);
        if (lane == 0) part[blockIdx.x] = s;
    }
}

__global__ void k_scanpart(int* part, int nb) {
    __shared__ int sh[NPART];
    int tid = threadIdx.x;
    sh[tid] = (tid < nb) ? part[tid] : 0;
    __syncthreads();
    for (int d = 1; d < NPART; d <<= 1) {
        int v = (tid >= d) ? sh[tid - d] : 0;
        __syncthreads();
        sh[tid] += v;
        __syncthreads();
    }
    if (tid < nb) part[tid] = (tid == 0) ? 0 : sh[tid - 1];
}

__global__ void k_off(int* cnt, const int* __restrict__ part, int* off,
                      float* dinv, int n) {
    __shared__ int wsum[16];
    int i = blockIdx.x * blockDim.x + threadIdx.x;
    int lane = threadIdx.x & 31, wid = threadIdx.x >> 5;
    int nw = blockDim.x >> 5;
    int v = (i < n) ? cnt[i] : 0;
    int x = v;
    #pragma unroll
    for (int d = 1; d < 32; d <<= 1) {
        int y = __shfl_up_sync(0xffffffffu, x, d);
        if (lane >= d) x += y;
    }
    if (lane == 31) wsum[wid] = x;
    __syncthreads();
    if (wid == 0) {
        int s = (lane < nw) ? wsum[lane] : 0;
        #pragma unroll
        for (int d = 1; d < 32; d <<= 1) {
            int y = __shfl_up_sync(0xffffffffu, s, d);
            if (lane >= d) s += y;
        }
        wsum[lane] = s;
    }
    __syncthreads();
    int excl = x - v + ((wid == 0) ? 0 : wsum[wid - 1]) + part[blockIdx.x];
    if (i < n) {
        off[i]  = excl;
        dinv[i] = rsqrtf((float)(v + 1));
        cnt[i]  = excl;          // cursor for fill
        if (i == n - 1) off[n] = excl + v;
    }
}

__global__ void k_fill(const int* __restrict__ src, const int* __restrict__ dst,
                       int* cnt, int* csr, int e) {
    int i = blockIdx.x * blockDim.x + threadIdx.x;
    if (i < e) {
        int d = dst[i];
        int pos = atomicAdd(&cnt[d], 1);
        csr[pos] = src[i];
    }
}

// ---------------- packed-f32x2 GEMM + dinv prescale + fp16 epilogue ---------
// out_h[r][c] = half( dinv[r] * (A[r,:]@W[:,c]) ); A input fp32 or fp16.
__device__ __forceinline__ void fma_f32x2(unsigned long long& d,
                                          unsigned long long a,
                                          unsigned long long b) {
    asm("fma.rn.f32x2 %0, %1, %2, %0;" : "+l"(d) : "l"(a), "l"(b));
}

template <int FP16IN>
__global__ __launch_bounds__(256) void k_gemm_p2(
        const void* __restrict__ Ain, const float* __restrict__ W,
        const float* __restrict__ dinv, __half* __restrict__ out, int M) {
    extern __shared__ float sm[];
    float2* Ws2 = (float2*)sm;            // [64][128] float2 = 64KB
    float*  As  = sm + 64 * 128 * 2;      // [64][128] float  = 32KB
    int tid = threadIdx.x;

    for (int i = tid; i < 64 * 32; i += 256) {
        int kp = i >> 5, c4 = i & 31;
        float4 w0 = ((const float4*)W)[(2 * kp)     * 32 + c4];
        float4 w1 = ((const float4*)W)[(2 * kp + 1) * 32 + c4];
        float2* dstp = Ws2 + kp * 128 + (c4 << 2);
        dstp[0] = make_float2(w0.x, w1.x);
        dstp[1] = make_float2(w0.y, w1.y);
        dstp[2] = make_float2(w0.z, w1.z);
        dstp[3] = make_float2(w0.w, w1.w);
    }
    int rowbase = blockIdx.x * 64;
    if (FP16IN) {
        const uint4* A4 = (const uint4*)Ain;       // 16B = 8 halfs; 16 per row
        for (int i = tid; i < 64 * 16; i += 256) {
            int r = i >> 4, c8 = i & 15;
            float4 f0 = make_float4(0.f, 0.f, 0.f, 0.f);
            float4 f1 = make_float4(0.f, 0.f, 0.f, 0.f);
            if (rowbase + r < M) {
                uint4 v = A4[(size_t)(rowbase + r) * 16 + c8];
                const __half2* h = (const __half2*)&v;
                float2 p0 = __half22float2(h[0]);
                float2 p1 = __half22float2(h[1]);
                float2 p2 = __half22float2(h[2]);
                float2 p3 = __half22float2(h[3]);
                f0 = make_float4(p0.x, p0.y, p1.x, p1.y);
                f1 = make_float4(p2.x, p2.y, p3.x, p3.y);
            }
            *(float4*)(As + r * 128 + c8 * 8)     = f0;
            *(float4*)(As + r * 128 + c8 * 8 + 4) = f1;
        }
    } else {
        const float4* A4 = (const float4*)Ain;
        for (int i = tid; i < 64 * 32; i += 256) {
            int r = i >> 5, c4 = i & 31;
            float4 v = make_float4(0.f, 0.f, 0.f, 0.f);
            if (rowbase + r < M) v = A4[(size_t)(rowbase + r) * 32 + c4];
            *(float4*)(As + r * 128 + (c4 << 2)) = v;
        }
    }
    __syncthreads();

    int lane = tid & 31, w = tid >> 5;
    unsigned long long acc[8][4];
    #pragma unroll
    for (int r = 0; r < 8; r++)
        #pragma unroll
        for (int j = 0; j < 4; j++) acc[r][j] = 0ull;

    const unsigned long long* Wsu = (const unsigned long long*)Ws2;
    #pragma unroll 4
    for (int kp = 0; kp < 64; kp++) {
        unsigned long long w2[4];
        #pragma unroll
        for (int j = 0; j < 4; j++) w2[j] = Wsu[kp * 128 + lane + 32 * j];
        #pragma unroll
        for (int r = 0; r < 8; r++) {
            unsigned long long a2 =
                *(const unsigned long long*)(As + (w + r * 8) * 128 + 2 * kp);
            #pragma unroll
            for (int j = 0; j < 4; j++) fma_f32x2(acc[r][j], a2, w2[j]);
        }
    }

    #pragma unroll
    for (int r = 0; r < 8; r++) {
        int row = rowbase + w + r * 8;
        if (row < M) {
            float dv = dinv[row];
            #pragma unroll
            for (int j = 0; j < 4; j++) {
                unsigned long long u = acc[r][j];
                float lo = __uint_as_float((unsigned int)(u & 0xffffffffu));
                float hi = __uint_as_float((unsigned int)(u >> 32));
                out[row * 128 + lane + 32 * j] = __float2half_rn(dv * (lo + hi));
            }
        }
    }
}
#define GEMM_SMEM ((64 * 128 * 2 + 64 * 128) * sizeof(float))

// ---------------- gather: warp per node, fp16 in / fp16 out -----------------
// out[v] = relu( dinv[v] * (sum_{u in N(v)} P[u] + P[v]) + bias ) [+ residual]
__global__ void k_gather(const uint2* __restrict__ P, const float* __restrict__ bias,
                         const uint2* __restrict__ Hres, uint2* __restrict__ out,
                         const int* __restrict__ off, const int* __restrict__ csr,
                         const float* __restrict__ dinv, int n, int mode) {
    int gw = (blockIdx.x * blockDim.x + threadIdx.x) >> 5;
    if (gw >= n) return;
    int lane = threadIdx.x & 31;
    int v = gw;
    int off0 = off[v], off1 = off[v + 1];
    float dv = dinv[v];
    uint2 bu = P[v * 32 + lane];
    const __half2* bh = (const __half2*)&bu;
    float2 b0 = __half22float2(bh[0]);
    float2 b1 = __half22float2(bh[1]);
    float4 acc = make_float4(b0.x, b0.y, b1.x, b1.y);   // self term P[v]
    for (int j = off0; j < off1; j += 32) {
        int idx = j + lane;
        int u = (idx < off1) ? csr[idx] : 0;
        int m = off1 - j; if (m > 32) m = 32;
        #pragma unroll 4
        for (int i = 0; i < m; i++) {
            int uu = __shfl_sync(0xffffffffu, u, i);
            uint2 hu = P[uu * 32 + lane];
            const __half2* hh = (const __half2*)&hu;
            float2 f0 = __half22float2(hh[0]);
            float2 f1 = __half22float2(hh[1]);
            acc.x += f0.x; acc.y += f0.y;
            acc.z += f1.x; acc.w += f1.y;
        }
    }
    const float4* b4 = (const float4*)bias;
    float4 bb = b4[lane];
    float4 r;
    r.x = fmaxf(fmaf(dv, acc.x, bb.x), 0.f);
    r.y = fmaxf(fmaf(dv, acc.y, bb.y), 0.f);
    r.z = fmaxf(fmaf(dv, acc.z, bb.z), 0.f);
    r.w = fmaxf(fmaf(dv, acc.w, bb.w), 0.f);
    if (mode == 1) {
        uint2 hres = Hres[v * 32 + lane];
        const __half2* hh = (const __half2*)&hres;
        float2 h0 = __half22float2(hh[0]);
        float2 h1 = __half22float2(hh[1]);
        r.x += h0.x; r.y += h0.y; r.z += h1.x; r.w += h1.y;
    }
    uint2 o;
    __half2* oh = (__half2*)&o;
    oh[0] = __floats2half2_rn(r.x, r.y);
    oh[1] = __floats2half2_rn(r.z, r.w);
    out[v * 32 + lane] = o;
}

// ---------------- pooling (fp16 H; binary-search bounds) --------------------
__global__ void k_pool(const uint2* __restrict__ H, float4* __restrict__ pool,
                       const int* __restrict__ batch, int n, int g) {
    int gw = (blockIdx.x * blockDim.x + threadIdx.x) >> 5;
    if (gw >= g) return;
    int lane = threadIdx.x & 31;
    int lo = 0, hi = n;
    while (lo < hi) { int mid = (lo + hi) >> 1; if (batch[mid] < gw) lo = mid + 1; else hi = mid; }
    int s = lo;
    hi = n;
    while (lo < hi) { int mid = (lo + hi) >> 1; if (batch[mid] < gw + 1) lo = mid + 1; else hi = mid; }
    int e = lo;
    float4 acc = make_float4(0.f, 0.f, 0.f, 0.f);
    for (int r = s; r < e; r++) {
        uint2 hv = H[r * 32 + lane];
        const __half2* hh = (const __half2*)&hv;
        float2 f0 = __half22float2(hh[0]);
        float2 f1 = __half22float2(hh[1]);
        acc.x += f0.x; acc.y += f0.y; acc.z += f1.x; acc.w += f1.y;
    }
    float sc = (e > s) ? 1.0f / (float)(e - s) : 0.f;
    pool[gw * 32 + lane] = make_float4(acc.x * sc, acc.y * sc, acc.z * sc, acc.w * sc);
}

// ---------------- small GEMM: warp per row ----------------
template <int NPER>
__global__ void k_gemm_small(const float* __restrict__ A, const float* __restrict__ W,
                             const float* __restrict__ bias, float* __restrict__ out,
                             int M, int K, int N, int relu) {
    int gw = (blockIdx.x * blockDim.x + threadIdx.x) >> 5;
    if (gw >= M) return;
    int lane = threadIdx.x & 31;
    float acc[NPER];
    #pragma unroll
    for (int j = 0; j < NPER; j++) acc[j] = 0.f;
    const float* a = A + gw * K;
    for (int k = 0; k < K; k++) {
        float av = __ldg(a + k);
        const float* wr = W + k * N;
        #pragma unroll
        for (int j = 0; j < NPER; j++) acc[j] += av * __ldg(wr + lane + 32 * j);
    }
    #pragma unroll
    for (int j = 0; j < NPER; j++) {
        float v = acc[j] + bias[lane + 32 * j];
        if (relu) v = fmaxf(v, 0.f);
        out[gw * N + lane + 32 * j] = v;
    }
}

// ---------------- batchnorm ----------------
__global__ void k_bn(const float* __restrict__ x, const float* __restrict__ gamma,
                     const float* __restrict__ beta, float* __restrict__ out,
                     int rows, int cols, int relu) {
    int col = blockIdx.x;
    int tid = threadIdx.x, lane = tid & 31, wid = tid >> 5;
    __shared__ float red[8];
    __shared__ float s_m, s_inv;
    float s = 0.f, s2 = 0.f;
    for (int r = tid; r < rows; r += blockDim.x) {
        float v = x[r * cols + col];
        s += v; s2 += v * v;
    }
    #pragma unroll
    for (int o = 16; o; o >>= 1) {
        s  += __shfl_down_sync(0xffffffffu, s, o);
        s2 += __shfl_down_sync(0xffffffffu, s2, o);
    }
    if (lane == 0) { red[wid] = s; red[4 + wid] = s2; }
    __syncthreads();
    if (tid == 0) {
        float ts = red[0] + red[1] + red[2] + red[3];
        float t2 = red[4] + red[5] + red[6] + red[7];
        float m = ts / rows;
        float var = t2 / rows - m * m;
        s_m = m;
        s_inv = rsqrtf(var + 1e-5f);
    }
    __syncthreads();
    float m = s_m, inv = s_inv, ga = gamma[col], be = beta[col];
    for (int r = tid; r < rows; r += blockDim.x) {
        float v = ga * (x[r * cols + col] - m) * inv + be;
        if (relu) v = fmaxf(v, 0.f);
        out[r * cols + col] = v;
    }
}

// ---------------- host orchestration ----------------
struct HeadW {
    const float *Wp1, *bp1, *ga1, *be1, *Wp2, *bp2, *ga2, *be2;
    const float *Wq1, *bq1, *Wq2, *bq2;
};

static void run_encoder_and_head(cudaStream_t st, EncScratch* S,
        const float* x, const int* ei, const int* batch,
        const float* W1, const float* b1, const float* W2, const float* b2,
        const float* W3, const float* b3, const HeadW& hw,
        float* pout, float* zout, int n, int e, int g) {
    const int* src = ei;
    const int* dst = ei + e;

    int tb = 256;
    int nb512 = (n + 511) / 512;
    k_zero  <<<(n + tb - 1) / tb, tb, 0, st>>>(S->cnt, n);
    k_degree<<<(e + tb - 1) / tb, tb, 0, st>>>(dst, S->cnt, e);
    k_part  <<<nb512, 512, 0, st>>>(S->cnt, S->part, n);
    k_scanpart<<<1, NPART, 0, st>>>(S->part, nb512);
    k_off   <<<nb512, 512, 0, st>>>(S->cnt, S->part, S->off, S->dinv, n);
    k_fill  <<<(e + tb - 1) / tb, tb, 0, st>>>(src, dst, S->cnt, S->csr, e);

    int gemm_grid = (n + 63) / 64;
    int gath_grid = (n * 32 + tb - 1) / tb;

    const uint2* Ph = (const uint2*)S->Ph;
    uint2* Ha = (uint2*)S->Ha;
    uint2* Hb = (uint2*)S->Hb;

    k_gemm_p2<0><<<gemm_grid, 256, GEMM_SMEM, st>>>(x, W1, S->dinv, S->Ph, n);
    k_gather<<<gath_grid, tb, 0, st>>>(Ph, b1, nullptr, Ha, S->off, S->csr, S->dinv, n, 0);
    k_gemm_p2<1><<<gemm_grid, 256, GEMM_SMEM, st>>>(S->Ha, W2, S->dinv, S->Ph, n);
    k_gather<<<gath_grid, tb, 0, st>>>(Ph, b2, (const uint2*)Ha, Hb, S->off, S->csr, S->dinv, n, 1);
    k_gemm_p2<1><<<gemm_grid, 256, GEMM_SMEM, st>>>(S->Hb, W3, S->dinv, S->Ph, n);
    k_gather<<<gath_grid, tb, 0, st>>>(Ph, b3, (const uint2*)Hb, Ha, S->off, S->csr, S->dinv, n, 1);

    k_pool<<<(g * 32 + tb - 1) / tb, tb, 0, st>>>((const uint2*)Ha, (float4*)S->pool,
                                                  batch, n, g);

    // head
    int gw_blocks = (g * 32 + 255) / 256;
    k_gemm_small<8><<<gw_blocks, 256, 0, st>>>(S->pool, hw.Wp1, hw.bp1, S->t, g, HID, PROJ, 0);
    k_bn<<<PROJ, 128, 0, st>>>(S->t, hw.ga1, hw.be1, S->t, g, PROJ, 1);
    k_gemm_small<8><<<gw_blocks, 256, 0, st>>>(S->t, hw.Wp2, hw.bp2, S->t2, g, PROJ, PROJ, 0);
    k_bn<<<PROJ, 128, 0, st>>>(S->t2, hw.ga2, hw.be2, zout, g, PROJ, 0);
    k_gemm_small<4><<<gw_blocks, 256, 0, st>>>(zout, hw.Wq1, hw.bq1, S->q, g, PROJ, PROJ / 2, 1);
    k_gemm_small<8><<<gw_blocks, 256, 0, st>>>(S->q, hw.Wq2, hw.bq2, pout, g, PROJ / 2, PROJ, 0);
}

extern "C" void kernel_launch(void* const* d_in, const int* in_sizes, int n_in,
                              void* d_out, int out_size) {
    const float* x1  = (const float*)d_in[0];
    const int*   ei1 = (const int*)  d_in[1];
    const int*   bt1 = (const int*)  d_in[2];
    const float* x2  = (const float*)d_in[3];
    const int*   ei2 = (const int*)  d_in[4];
    const int*   bt2 = (const int*)  d_in[5];
    const float* W1  = (const float*)d_in[6];
    const float* b1  = (const float*)d_in[7];
    const float* W2  = (const float*)d_in[8];
    const float* b2  = (const float*)d_in[9];
    const float* W3  = (const float*)d_in[10];
    const float* b3  = (const float*)d_in[11];
    HeadW hw;
    hw.Wp1 = (const float*)d_in[12]; hw.bp1 = (const float*)d_in[13];
    hw.ga1 = (const float*)d_in[14]; hw.be1 = (const float*)d_in[15];
    hw.Wp2 = (const float*)d_in[16]; hw.bp2 = (const float*)d_in[17];
    hw.ga2 = (const float*)d_in[18]; hw.be2 = (const float*)d_in[19];
    hw.Wq1 = (const float*)d_in[20]; hw.bq1 = (const float*)d_in[21];
    hw.Wq2 = (const float*)d_in[22]; hw.bq2 = (const float*)d_in[23];

    int n = in_sizes[0] / INF_;
    int e = in_sizes[1] / 2;
    int g = GG;

    static bool init = false;
    static cudaStream_t s2;
    static cudaEvent_t evFork, evJoin;
    if (!init) {
        cudaStreamCreateWithFlags(&s2, cudaStreamNonBlocking);
        cudaEventCreateWithFlags(&evFork, cudaEventDisableTiming);
        cudaEventCreateWithFlags(&evJoin, cudaEventDisableTiming);
        cudaFuncSetAttribute(k_gemm_p2<0>, cudaFuncAttributeMaxDynamicSharedMemorySize,
                             GEMM_SMEM);
        cudaFuncSetAttribute(k_gemm_p2<1>, cudaFuncAttributeMaxDynamicSharedMemorySize,
                             GEMM_SMEM);
        init = true;
    }

    EncScratch *S0, *S1;
    cudaGetSymbolAddress((void**)&S0, g_e0);
    cudaGetSymbolAddress((void**)&S1, g_e1);

    float* out = (float*)d_out;
    float* p1 = out;
    float* p2 = out + g * PROJ;
    float* z1 = out + 2 * g * PROJ;
    float* z2 = out + 3 * g * PROJ;

    // fork
    cudaEventRecord(evFork, 0);
    cudaStreamWaitEvent(s2, evFork, 0);

    run_encoder_and_head(0,  S0, x1, ei1, bt1, W1, b1, W2, b2, W3, b3, hw, p1, z1, n, e, g);
    run_encoder_and_head(s2, S1, x2, ei2, bt2, W1, b1, W2, b2, W3, b3, hw, p2, z2, n, e, g);

    // join
    cudaEventRecord(evJoin, s2);
    cudaStreamWaitEvent(0, evJoin, 0);
}

// round 17
// speedup vs baseline: 1.0915x; 1.0260x over previous
#include <cuda_runtime.h>
#include <cuda_bf16.h>
#include <cuda_fp16.h>
#include <math.h>

// Problem constants
#define NN 50000
#define EE 1600000
#define GG 512
#define INF_ 128
#define HID 128
#define PROJ 256
#define NPART 128   // >= ceil(NN/512)

// ---------------- device scratch, duplicated per encoder ----------------
// All vector-cast arrays first (16B-multiple sizes); odd-sized off[] last.
struct alignas(16) EncScratch {
    __half Ph[NN * HID];      // fp16 prescaled features dinv[u]*(A@W)[u]
    __half Ha[NN * HID];      // fp16 hidden states (halved footprint: fits L2)
    __half Hb[NN * HID];
    float pool[GG * HID];
    float t [GG * PROJ];
    float t2[GG * PROJ];
    float q [GG * (PROJ/2)];
    float dinv[NN];
    int   cnt[NN];
    int   csr[EE];
    int   part[NPART];
    int   off[NN + 1];        // odd size -> keep last
};
__device__ EncScratch g_e0;
__device__ EncScratch g_e1;

// ---------------- CSR build ----------------
__global__ void k_zero(int* cnt, int n) {
    int i = blockIdx.x * blockDim.x + threadIdx.x;
    if (i < n) cnt[i] = 0;
}

__global__ void k_degree(const int* __restrict__ dst, int* cnt, int e) {
    int i = blockIdx.x * blockDim.x + threadIdx.x;
    if (i < e) atomicAdd(&cnt[dst[i]], 1);
}

__global__ void k_part(const int* __restrict__ cnt, int* part, int n) {
    __shared__ int red[16];
    int i = blockIdx.x * blockDim.x + threadIdx.x;
    int v = (i < n) ? cnt[i] : 0;
    int lane = threadIdx.x & 31, wid = threadIdx.x >> 5;
    #pragma unroll
    for (int o = 16; o; o >>= 1) v += __shfl_down_sync(0xffffffffu, v, o);
    if (lane == 0) red[wid] = v;
    __syncthreads();
    if (wid == 0) {
        int s = (lane < (blockDim.x >> 5)) ? red[lane] : 0;
        #pragma unroll
        for (int o = 16; o; o >>= 1) s += __shfl_down_sync(0xffffffffu, s, o);
        if (lane == 0) part[blockIdx.x] = s;
    }
}

__global__ void k_scanpart(int* part, int nb) {
    __shared__ int sh[NPART];
    int tid = threadIdx.x;
    sh[tid] = (tid < nb) ? part[tid] : 0;
    __syncthreads();
    for (int d = 1; d < NPART; d <<= 1) {
        int v = (tid >= d) ? sh[tid - d] : 0;
        __syncthreads();
        sh[tid] += v;
        __syncthreads();
    }
    if (tid < nb) part[tid] = (tid == 0) ? 0 : sh[tid - 1];
}

__global__ void k_off(int* cnt, const int* __restrict__ part, int* off,
                      float* dinv, int n) {
    __shared__ int wsum[16];
    int i = blockIdx.x * blockDim.x + threadIdx.x;
    int lane = threadIdx.x & 31, wid = threadIdx.x >> 5;
    int nw = blockDim.x >> 5;
    int v = (i < n) ? cnt[i] : 0;
    int x = v;
    #pragma unroll
    for (int d = 1; d < 32; d <<= 1) {
        int y = __shfl_up_sync(0xffffffffu, x, d);
        if (lane >= d) x += y;
    }
    if (lane == 31) wsum[wid] = x;
    __syncthreads();
    if (wid == 0) {
        int s = (lane < nw) ? wsum[lane] : 0;
        #pragma unroll
        for (int d = 1; d < 32; d <<= 1) {
            int y = __shfl_up_sync(0xffffffffu, s, d);
            if (lane >= d) s += y;
        }
        wsum[lane] = s;
    }
    __syncthreads();
    int excl = x - v + ((wid == 0) ? 0 : wsum[wid - 1]) + part[blockIdx.x];
    if (i < n) {
        off[i]  = excl;
        dinv[i] = rsqrtf((float)(v + 1));
        cnt[i]  = excl;          // cursor for fill
        if (i == n - 1) off[n] = excl + v;
    }
}

__global__ void k_fill(const int* __restrict__ src, const int* __restrict__ dst,
                       int* cnt, int* csr, int e) {
    int i = blockIdx.x * blockDim.x + threadIdx.x;
    if (i < e) {
        int d = dst[i];
        int pos = atomicAdd(&cnt[d], 1);
        csr[pos] = src[i];
    }
}

// ---------------- packed-f32x2 GEMM + dinv prescale + fp16 epilogue ---------
// out_h[r][c] = half( dinv[r] * (A[r,:]@W[:,c]) ); A input fp32 or fp16.
__device__ __forceinline__ void fma_f32x2(unsigned long long& d,
                                          unsigned long long a,
                                          unsigned long long b) {
    asm("fma.rn.f32x2 %0, %1, %2, %0;" : "+l"(d) : "l"(a), "l"(b));
}

template <int FP16IN>
__global__ __launch_bounds__(256) void k_gemm_p2(
        const void* __restrict__ Ain, const float* __restrict__ W,
        const float* __restrict__ dinv, __half* __restrict__ out, int M) {
    extern __shared__ float sm[];
    float2* Ws2 = (float2*)sm;            // [64][128] float2 = 64KB
    float*  As  = sm + 64 * 128 * 2;      // [64][128] float  = 32KB
    int tid = threadIdx.x;

    for (int i = tid; i < 64 * 32; i += 256) {
        int kp = i >> 5, c4 = i & 31;
        float4 w0 = ((const float4*)W)[(2 * kp)     * 32 + c4];
        float4 w1 = ((const float4*)W)[(2 * kp + 1) * 32 + c4];
        float2* dstp = Ws2 + kp * 128 + (c4 << 2);
        dstp[0] = make_float2(w0.x, w1.x);
        dstp[1] = make_float2(w0.y, w1.y);
        dstp[2] = make_float2(w0.z, w1.z);
        dstp[3] = make_float2(w0.w, w1.w);
    }
    int rowbase = blockIdx.x * 64;
    if (FP16IN) {
        const uint4* A4 = (const uint4*)Ain;       // 16B = 8 halfs; 16 per row
        for (int i = tid; i < 64 * 16; i += 256) {
            int r = i >> 4, c8 = i & 15;
            float4 f0 = make_float4(0.f, 0.f, 0.f, 0.f);
            float4 f1 = make_float4(0.f, 0.f, 0.f, 0.f);
            if (rowbase + r < M) {
                uint4 v = A4[(size_t)(rowbase + r) * 16 + c8];
                const __half2* h = (const __half2*)&v;
                float2 p0 = __half22float2(h[0]);
                float2 p1 = __half22float2(h[1]);
                float2 p2 = __half22float2(h[2]);
                float2 p3 = __half22float2(h[3]);
                f0 = make_float4(p0.x, p0.y, p1.x, p1.y);
                f1 = make_float4(p2.x, p2.y, p3.x, p3.y);
            }
            *(float4*)(As + r * 128 + c8 * 8)     = f0;
            *(float4*)(As + r * 128 + c8 * 8 + 4) = f1;
        }
    } else {
        const float4* A4 = (const float4*)Ain;
        for (int i = tid; i < 64 * 32; i += 256) {
            int r = i >> 5, c4 = i & 31;
            float4 v = make_float4(0.f, 0.f, 0.f, 0.f);
            if (rowbase + r < M) v = A4[(size_t)(rowbase + r) * 32 + c4];
            *(float4*)(As + r * 128 + (c4 << 2)) = v;
        }
    }
    __syncthreads();

    int lane = tid & 31, w = tid >> 5;
    unsigned long long acc[8][4];
    #pragma unroll
    for (int r = 0; r < 8; r++)
        #pragma unroll
        for (int j = 0; j < 4; j++) acc[r][j] = 0ull;

    const unsigned long long* Wsu = (const unsigned long long*)Ws2;
    #pragma unroll 4
    for (int kp = 0; kp < 64; kp++) {
        unsigned long long w2[4];
        #pragma unroll
        for (int j = 0; j < 4; j++) w2[j] = Wsu[kp * 128 + lane + 32 * j];
        #pragma unroll
        for (int r = 0; r < 8; r++) {
            unsigned long long a2 =
                *(const unsigned long long*)(As + (w + r * 8) * 128 + 2 * kp);
            #pragma unroll
            for (int j = 0; j < 4; j++) fma_f32x2(acc[r][j], a2, w2[j]);
        }
    }

    #pragma unroll
    for (int r = 0; r < 8; r++) {
        int row = rowbase + w + r * 8;
        if (row < M) {
            float dv = dinv[row];
            #pragma unroll
            for (int j = 0; j < 4; j++) {
                unsigned long long u = acc[r][j];
                float lo = __uint_as_float((unsigned int)(u & 0xffffffffu));
                float hi = __uint_as_float((unsigned int)(u >> 32));
                out[row * 128 + lane + 32 * j] = __float2half_rn(dv * (lo + hi));
            }
        }
    }
}
#define GEMM_SMEM ((64 * 128 * 2 + 64 * 128) * sizeof(float))

// ---------------- gather: warp per node, fp16, software-pipelined -----------
// Full 32-edge chunks run a fixed-trip unchecked loop; csr chunk j+32 is
// prefetched while chunk j is processed; single bounded tail chunk at the end.
__global__ void k_gather(const uint2* __restrict__ P, const float* __restrict__ bias,
                         const uint2* __restrict__ Hres, uint2* __restrict__ out,
                         const int* __restrict__ off, const int* __restrict__ csr,
                         const float* __restrict__ dinv, int n, int mode) {
    int gw = (blockIdx.x * blockDim.x + threadIdx.x) >> 5;
    if (gw >= n) return;
    int lane = threadIdx.x & 31;
    int v = gw;
    int off0 = off[v], off1 = off[v + 1];
    float dv = dinv[v];
    uint2 bu = P[v * 32 + lane];
    const __half2* bh = (const __half2*)&bu;
    float2 b0 = __half22float2(bh[0]);
    float2 b1 = __half22float2(bh[1]);
    float4 acc = make_float4(b0.x, b0.y, b1.x, b1.y);   // self term P[v]

    int j = off0;
    int u = (j + lane < off1) ? csr[j + lane] : 0;
    // full chunks: fixed 32 iterations, no bounds checks; prefetch next chunk
    for (; j + 32 <= off1; j += 32) {
        int un = (j + 32 + lane < off1) ? csr[j + 32 + lane] : 0;
        #pragma unroll 8
        for (int i = 0; i < 32; i++) {
            int uu = __shfl_sync(0xffffffffu, u, i);
            uint2 hu = P[uu * 32 + lane];
            const __half2* hh = (const __half2*)&hu;
            float2 f0 = __half22float2(hh[0]);
            float2 f1 = __half22float2(hh[1]);
            acc.x += f0.x; acc.y += f0.y;
            acc.z += f1.x; acc.w += f1.y;
        }
        u = un;
    }
    // tail chunk (< 32 edges)
    int m = off1 - j;
    #pragma unroll 4
    for (int i = 0; i < m; i++) {
        int uu = __shfl_sync(0xffffffffu, u, i);
        uint2 hu = P[uu * 32 + lane];
        const __half2* hh = (const __half2*)&hu;
        float2 f0 = __half22float2(hh[0]);
        float2 f1 = __half22float2(hh[1]);
        acc.x += f0.x; acc.y += f0.y;
        acc.z += f1.x; acc.w += f1.y;
    }

    const float4* b4 = (const float4*)bias;
    float4 bb = b4[lane];
    float4 r;
    r.x = fmaxf(fmaf(dv, acc.x, bb.x), 0.f);
    r.y = fmaxf(fmaf(dv, acc.y, bb.y), 0.f);
    r.z = fmaxf(fmaf(dv, acc.z, bb.z), 0.f);
    r.w = fmaxf(fmaf(dv, acc.w, bb.w), 0.f);
    if (mode == 1) {
        uint2 hres = Hres[v * 32 + lane];
        const __half2* hh = (const __half2*)&hres;
        float2 h0 = __half22float2(hh[0]);
        float2 h1 = __half22float2(hh[1]);
        r.x += h0.x; r.y += h0.y; r.z += h1.x; r.w += h1.y;
    }
    uint2 o;
    __half2* oh = (__half2*)&o;
    oh[0] = __floats2half2_rn(r.x, r.y);
    oh[1] = __floats2half2_rn(r.z, r.w);
    out[v * 32 + lane] = o;
}

// ---------------- pooling: BLOCK per graph (4 warps split rows) -------------
__global__ void k_pool(const uint2* __restrict__ H, float4* __restrict__ pool,
                       const int* __restrict__ batch, int n, int g) {
    int gid = blockIdx.x;
    if (gid >= g) return;
    int lane = threadIdx.x & 31, wid = threadIdx.x >> 5;
    int lo = 0, hi = n;
    while (lo < hi) { int mid = (lo + hi) >> 1; if (batch[mid] < gid) lo = mid + 1; else hi = mid; }
    int s = lo;
    hi = n;
    while (lo < hi) { int mid = (lo + hi) >> 1; if (batch[mid] < gid + 1) lo = mid + 1; else hi = mid; }
    int e = lo;
    float4 acc = make_float4(0.f, 0.f, 0.f, 0.f);
    for (int r = s + wid; r < e; r += 4) {
        uint2 hv = H[r * 32 + lane];
        const __half2* hh = (const __half2*)&hv;
        float2 f0 = __half22float2(hh[0]);
        float2 f1 = __half22float2(hh[1]);
        acc.x += f0.x; acc.y += f0.y; acc.z += f1.x; acc.w += f1.y;
    }
    __shared__ float4 red[4][32];
    red[wid][lane] = acc;
    __syncthreads();
    if (wid == 0) {
        float4 a = red[0][lane], b = red[1][lane], c = red[2][lane], d = red[3][lane];
        float sc = (e > s) ? 1.0f / (float)(e - s) : 0.f;
        pool[gid * 32 + lane] = make_float4((a.x + b.x + c.x + d.x) * sc,
                                            (a.y + b.y + c.y + d.y) * sc,
                                            (a.z + b.z + c.z + d.z) * sc,
                                            (a.w + b.w + c.w + d.w) * sc);
    }
}

// ---------------- small GEMM: warp per row ----------------
template <int NPER>
__global__ void k_gemm_small(const float* __restrict__ A, const float* __restrict__ W,
                             const float* __restrict__ bias, float* __restrict__ out,
                             int M, int K, int N, int relu) {
    int gw = (blockIdx.x * blockDim.x + threadIdx.x) >> 5;
    if (gw >= M) return;
    int lane = threadIdx.x & 31;
    float acc[NPER];
    #pragma unroll
    for (int j = 0; j < NPER; j++) acc[j] = 0.f;
    const float* a = A + gw * K;
    for (int k = 0; k < K; k++) {
        float av = __ldg(a + k);
        const float* wr = W + k * N;
        #pragma unroll
        for (int j = 0; j < NPER; j++) acc[j] += av * __ldg(wr + lane + 32 * j);
    }
    #pragma unroll
    for (int j = 0; j < NPER; j++) {
        float v = acc[j] + bias[lane + 32 * j];
        if (relu) v = fmaxf(v, 0.f);
        out[gw * N + lane + 32 * j] = v;
    }
}

// ---------------- batchnorm ----------------
__global__ void k_bn(const float* __restrict__ x, const float* __restrict__ gamma,
                     const float* __restrict__ beta, float* __restrict__ out,
                     int rows, int cols, int relu) {
    int col = blockIdx.x;
    int tid = threadIdx.x, lane = tid & 31, wid = tid >> 5;
    __shared__ float red[8];
    __shared__ float s_m, s_inv;
    float s = 0.f, s2 = 0.f;
    for (int r = tid; r < rows; r += blockDim.x) {
        float v = x[r * cols + col];
        s += v; s2 += v * v;
    }
    #pragma unroll
    for (int o = 16; o; o >>= 1) {
        s  += __shfl_down_sync(0xffffffffu, s, o);
        s2 += __shfl_down_sync(0xffffffffu, s2, o);
    }
    if (lane == 0) { red[wid] = s; red[4 + wid] = s2; }
    __syncthreads();
    if (tid == 0) {
        float ts = red[0] + red[1] + red[2] + red[3];
        float t2 = red[4] + red[5] + red[6] + red[7];
        float m = ts / rows;
        float var = t2 / rows - m * m;
        s_m = m;
        s_inv = rsqrtf(var + 1e-5f);
    }
    __syncthreads();
    float m = s_m, inv = s_inv, ga = gamma[col], be = beta[col];
    for (int r = tid; r < rows; r += blockDim.x) {
        float v = ga * (x[r * cols + col] - m) * inv + be;
        if (relu) v = fmaxf(v, 0.f);
        out[r * cols + col] = v;
    }
}

// ---------------- host orchestration ----------------
struct HeadW {
    const float *Wp1, *bp1, *ga1, *be1, *Wp2, *bp2, *ga2, *be2;
    const float *Wq1, *bq1, *Wq2, *bq2;
};

static void run_encoder_and_head(cudaStream_t st, EncScratch* S,
        const float* x, const int* ei, const int* batch,
        const float* W1, const float* b1, const float* W2, const float* b2,
        const float* W3, const float* b3, const HeadW& hw,
        float* pout, float* zout, int n, int e, int g) {
    const int* src = ei;
    const int* dst = ei + e;

    int tb = 256;
    int nb512 = (n + 511) / 512;
    k_zero  <<<(n + tb - 1) / tb, tb, 0, st>>>(S->cnt, n);
    k_degree<<<(e + tb - 1) / tb, tb, 0, st>>>(dst, S->cnt, e);
    k_part  <<<nb512, 512, 0, st>>>(S->cnt, S->part, n);
    k_scanpart<<<1, NPART, 0, st>>>(S->part, nb512);
    k_off   <<<nb512, 512, 0, st>>>(S->cnt, S->part, S->off, S->dinv, n);
    k_fill  <<<(e + tb - 1) / tb, tb, 0, st>>>(src, dst, S->cnt, S->csr, e);

    int gemm_grid = (n + 63) / 64;
    int gath_grid = (n * 32 + tb - 1) / tb;

    const uint2* Ph = (const uint2*)S->Ph;
    uint2* Ha = (uint2*)S->Ha;
    uint2* Hb = (uint2*)S->Hb;

    k_gemm_p2<0><<<gemm_grid, 256, GEMM_SMEM, st>>>(x, W1, S->dinv, S->Ph, n);
    k_gather<<<gath_grid, tb, 0, st>>>(Ph, b1, nullptr, Ha, S->off, S->csr, S->dinv, n, 0);
    k_gemm_p2<1><<<gemm_grid, 256, GEMM_SMEM, st>>>(S->Ha, W2, S->dinv, S->Ph, n);
    k_gather<<<gath_grid, tb, 0, st>>>(Ph, b2, (const uint2*)Ha, Hb, S->off, S->csr, S->dinv, n, 1);
    k_gemm_p2<1><<<gemm_grid, 256, GEMM_SMEM, st>>>(S->Hb, W3, S->dinv, S->Ph, n);
    k_gather<<<gath_grid, tb, 0, st>>>(Ph, b3, (const uint2*)Hb, Ha, S->off, S->csr, S->dinv, n, 1);

    k_pool<<<g, 128, 0, st>>>((const uint2*)Ha, (float4*)S->pool, batch, n, g);

    // head
    int gw_blocks = (g * 32 + 255) / 256;
    k_gemm_small<8><<<gw_blocks, 256, 0, st>>>(S->pool, hw.Wp1, hw.bp1, S->t, g, HID, PROJ, 0);
    k_bn<<<PROJ, 128, 0, st>>>(S->t, hw.ga1, hw.be1, S->t, g, PROJ, 1);
    k_gemm_small<8><<<gw_blocks, 256, 0, st>>>(S->t, hw.Wp2, hw.bp2, S->t2, g, PROJ, PROJ, 0);
    k_bn<<<PROJ, 128, 0, st>>>(S->t2, hw.ga2, hw.be2, zout, g, PROJ, 0);
    k_gemm_small<4><<<gw_blocks, 256, 0, st>>>(zout, hw.Wq1, hw.bq1, S->q, g, PROJ, PROJ / 2, 1);
    k_gemm_small<8><<<gw_blocks, 256, 0, st>>>(S->q, hw.Wq2, hw.bq2, pout, g, PROJ / 2, PROJ, 0);
}

extern "C" void kernel_launch(void* const* d_in, const int* in_sizes, int n_in,
                              void* d_out, int out_size) {
    const float* x1  = (const float*)d_in[0];
    const int*   ei1 = (const int*)  d_in[1];
    const int*   bt1 = (const int*)  d_in[2];
    const float* x2  = (const float*)d_in[3];
    const int*   ei2 = (const int*)  d_in[4];
    const int*   bt2 = (const int*)  d_in[5];
    const float* W1  = (const float*)d_in[6];
    const float* b1  = (const float*)d_in[7];
    const float* W2  = (const float*)d_in[8];
    const float* b2  = (const float*)d_in[9];
    const float* W3  = (const float*)d_in[10];
    const float* b3  = (const float*)d_in[11];
    HeadW hw;
    hw.Wp1 = (const float*)d_in[12]; hw.bp1 = (const float*)d_in[13];
    hw.ga1 = (const float*)d_in[14]; hw.be1 = (const float*)d_in[15];
    hw.Wp2 = (const float*)d_in[16]; hw.bp2 = (const float*)d_in[17];
    hw.ga2 = (const float*)d_in[18]; hw.be2 = (const float*)d_in[19];
    hw.Wq1 = (const float*)d_in[20]; hw.bq1 = (const float*)d_in[21];
    hw.Wq2 = (const float*)d_in[22]; hw.bq2 = (const float*)d_in[23];

    int n = in_sizes[0] / INF_;
    int e = in_sizes[1] / 2;
    int g = GG;

    static bool init = false;
    static cudaStream_t s2;
    static cudaEvent_t evFork, evJoin;
    if (!init) {
        cudaStreamCreateWithFlags(&s2, cudaStreamNonBlocking);
        cudaEventCreateWithFlags(&evFork, cudaEventDisableTiming);
        cudaEventCreateWithFlags(&evJoin, cudaEventDisableTiming);
        cudaFuncSetAttribute(k_gemm_p2<0>, cudaFuncAttributeMaxDynamicSharedMemorySize,
                             GEMM_SMEM);
        cudaFuncSetAttribute(k_gemm_p2<1>, cudaFuncAttributeMaxDynamicSharedMemorySize,
                             GEMM_SMEM);
        init = true;
    }

    EncScratch *S0, *S1;
    cudaGetSymbolAddress((void**)&S0, g_e0);
    cudaGetSymbolAddress((void**)&S1, g_e1);

    float* out = (float*)d_out;
    float* p1 = out;
    float* p2 = out + g * PROJ;
    float* z1 = out + 2 * g * PROJ;
    float* z2 = out + 3 * g * PROJ;

    // fork
    cudaEventRecord(evFork, 0);
    cudaStreamWaitEvent(s2, evFork, 0);

    run_encoder_and_head(0,  S0, x1, ei1, bt1, W1, b1, W2, b2, W3, b3, hw, p1, z1, n, e, g);
    run_encoder_and_head(s2, S1, x2, ei2, bt2, W1, b1, W2, b2, W3, b3, hw, p2, z2, n, e, g);

    // join
    cudaEventRecord(evJoin, s2);
    cudaStreamWaitEvent(0, evJoin, 0);
}